// round 16
// baseline (speedup 1.0000x reference)
#include <cuda_runtime.h>
#include <cuda_fp16.h>
#include <cstdint>

#define B_  4
#define L_  1024
#define D_  1024
#define H_  16
#define HD  64
#define NBH (B_ * H_)   // 64

// ---------------------------------------------------------------------------
// Static device scratch (no allocation allowed) — single fp16 everywhere
// ---------------------------------------------------------------------------
__device__ __half g_q_h[NBH * L_ * HD];
__device__ __half g_k_h[NBH * L_ * HD];
__device__ __half g_v_h[NBH * L_ * HD];

__device__ __half g_x_h[B_ * L_ * D_];
__device__ __half g_wqkv_h[3 * D_ * D_];
__device__ __half g_wout_h[D_ * D_];
__device__ __half g_att_h[B_ * L_ * D_];

// ---------------------------------------------------------------------------
// PTX helpers (base ISA only)
// ---------------------------------------------------------------------------
__device__ __forceinline__ uint32_t smem_u32(const void* p) {
    uint32_t a;
    asm("{ .reg .u64 t; cvta.to.shared.u64 t, %1; cvt.u32.u64 %0, t; }" : "=r"(a) : "l"(p));
    return a;
}

#define CP_ASYNC16(dst, src) \
    asm volatile("cp.async.cg.shared.global [%0], [%1], 16;" :: "r"(dst), "l"(src))
#define CP_COMMIT() asm volatile("cp.async.commit_group;" ::: "memory")
#define CP_WAIT0()  asm volatile("cp.async.wait_group 0;" ::: "memory")
#define CP_WAIT1()  asm volatile("cp.async.wait_group 1;" ::: "memory")

__device__ __forceinline__ void ldsm_x4(uint32_t& r0, uint32_t& r1, uint32_t& r2,
                                        uint32_t& r3, uint32_t addr) {
    asm volatile("ldmatrix.sync.aligned.m8n8.x4.shared.b16 {%0,%1,%2,%3}, [%4];"
                 : "=r"(r0), "=r"(r1), "=r"(r2), "=r"(r3) : "r"(addr));
}
__device__ __forceinline__ void ldsm_x4_t(uint32_t& r0, uint32_t& r1, uint32_t& r2,
                                          uint32_t& r3, uint32_t addr) {
    asm volatile("ldmatrix.sync.aligned.m8n8.x4.trans.shared.b16 {%0,%1,%2,%3}, [%4];"
                 : "=r"(r0), "=r"(r1), "=r"(r2), "=r"(r3) : "r"(addr));
}

__device__ __forceinline__ void mma_fp16(float* d, const uint32_t* a,
                                         uint32_t b0, uint32_t b1) {
    asm volatile(
        "mma.sync.aligned.m16n8k16.row.col.f32.f16.f16.f32 "
        "{%0,%1,%2,%3}, {%4,%5,%6,%7}, {%8,%9}, {%0,%1,%2,%3};"
        : "+f"(d[0]), "+f"(d[1]), "+f"(d[2]), "+f"(d[3])
        : "r"(a[0]), "r"(a[1]), "r"(a[2]), "r"(a[3]), "r"(b0), "r"(b1));
}

// fp32x4 -> packed fp16x4
__device__ __forceinline__ uint2 f4_to_h4(float4 v) {
    __half2 a = __floats2half2_rn(v.x, v.y);
    __half2 b = __floats2half2_rn(v.z, v.w);
    return make_uint2(*(uint32_t*)&a, *(uint32_t*)&b);
}
__device__ __forceinline__ uint32_t f2_to_h2(float a, float b) {
    __half2 h = __floats2half2_rn(a, b);
    return *(uint32_t*)&h;
}

// swizzled byte offset of float4-chunk c4 in a 128B-row 16-bit tile
__device__ __forceinline__ uint32_t sw_off4(int row, int c4) {
    return (uint32_t)(row * 128 + ((((c4 >> 1) ^ (row & 7)) << 4) | ((c4 & 1) << 3)));
}

// ---------------------------------------------------------------------------
// Merged fp32 -> fp16 conversion for x | w_qkv | w_out (one launch)
// ---------------------------------------------------------------------------
#define NX_CH (B_ * L_ * D_ / 4)
#define NW_CH (3 * D_ * D_ / 4)
#define NO_CH (D_ * D_ / 4)
#define CVT_CH (NX_CH + NW_CH + NO_CH)

__global__ void __launch_bounds__(256) cvt_all(const float* __restrict__ x,
                                               const float* __restrict__ wqkv,
                                               const float* __restrict__ wout) {
    int i = blockIdx.x * 256 + threadIdx.x;
    if (i < NX_CH) {
        ((uint2*)g_x_h)[i] = f4_to_h4(((const float4*)x)[i]);
    } else if (i < NX_CH + NW_CH) {
        int j = i - NX_CH;
        ((uint2*)g_wqkv_h)[j] = f4_to_h4(((const float4*)wqkv)[j]);
    } else if (i < CVT_CH) {
        int j = i - NX_CH - NW_CH;
        ((uint2*)g_wout_h)[j] = f4_to_h4(((const float4*)wout)[j]);
    }
}

// ---------------------------------------------------------------------------
// Warp-mma fp16 GEMM NT v7: CTA tile TM x 128 (TM=128 for gemm0, 64 for
// gemm1 to cut per-CTA wave time), 256 thr, 2 CTAs/SM, 3-stage cp.async.
// MODE 0: A=x, B=w_qkv -> scatter fp16 q/k/v.  MODE 1: A=att -> C fp32.
// ---------------------------------------------------------------------------
template <int MODE>
__global__ void __launch_bounds__(256, 2) tc_gemm(float* __restrict__ C) {
    constexpr int TM   = (MODE == 0) ? 128 : 64;
    constexpr int MI   = TM / 32;                  // m16 frags per warp
    constexpr int AT   = TM * 128;                 // A tile bytes
    constexpr int STG  = AT + 16384;               // + B tile (128x64 fp16)

    extern __shared__ char smc[];
    uint32_t sb = smem_u32(smc);

    const __half* A  = (MODE == 0) ? g_x_h : g_att_h;
    const __half* Bp = (MODE == 0) ? g_wqkv_h : g_wout_h;

    const int t = threadIdx.x, lane = t & 31, warp = t >> 5;
    const int wm = warp & 1, wn = warp >> 1;
    const int m0 = blockIdx.y * TM, n0 = blockIdx.x * 128;

    float acc[MI][4][4];
#pragma unroll
    for (int mi = 0; mi < MI; mi++)
#pragma unroll
        for (int ni = 0; ni < 4; ni++)
#pragma unroll
            for (int e = 0; e < 4; e++) acc[mi][ni][e] = 0.f;

    const int a_rb = wm * (TM / 2) + (lane & 15);
    const int a_cb = (lane >> 4);
    const int b_rb = wn * 32 + ((lane >> 4) * 8) + (lane & 7);
    const int b_cb = (lane >> 3) & 1;

    auto load_stage = [&](int it, int s) {
        uint32_t base = sb + s * STG;
        int k0 = it * 64;
#pragma unroll
        for (int j = 0; j < TM / 32; j++) {        // A: TM*8 chunks
            int c = t + 256 * j;
            int row = c >> 3, ch = c & 7;
            uint32_t so = (uint32_t)(row * 128 + ((ch ^ (row & 7)) << 4));
            CP_ASYNC16(base + so, A + (size_t)(m0 + row) * 1024 + ch * 8 + k0);
        }
#pragma unroll
        for (int j = 0; j < 4; j++) {              // B: 128*8 chunks
            int c = t + 256 * j;
            int row = c >> 3, ch = c & 7;
            uint32_t so = (uint32_t)(row * 128 + ((ch ^ (row & 7)) << 4));
            CP_ASYNC16(base + AT + so, Bp + (size_t)(n0 + row) * 1024 + ch * 8 + k0);
        }
        CP_COMMIT();
    };

    load_stage(0, 0);
    load_stage(1, 1);

    for (int it = 0; it < 16; it++) {
        int s = it % 3;
        if (it == 15) CP_WAIT0(); else CP_WAIT1();
        __syncthreads();
        if (it + 2 < 16) load_stage(it + 2, (it + 2) % 3);
        uint32_t base = sb + s * STG;

#pragma unroll
        for (int kk = 0; kk < 4; kk++) {
            uint32_t ah[MI][4];
#pragma unroll
            for (int mi = 0; mi < MI; mi++) {
                int r = a_rb + mi * 16;
                int c2 = kk * 2 + a_cb;
                uint32_t addr = base + (uint32_t)(r * 128 + ((c2 ^ (r & 7)) << 4));
                ldsm_x4(ah[mi][0], ah[mi][1], ah[mi][2], ah[mi][3], addr);
            }
#pragma unroll
            for (int nh = 0; nh < 2; nh++) {
                int r = b_rb + nh * 16;
                int c2 = kk * 2 + b_cb;
                uint32_t addr = base + AT
                              + (uint32_t)(r * 128 + ((c2 ^ (r & 7)) << 4));
                uint32_t bh[4];
                ldsm_x4(bh[0], bh[1], bh[2], bh[3], addr);
#pragma unroll
                for (int mi = 0; mi < MI; mi++)
#pragma unroll
                    for (int q = 0; q < 2; q++)
                        mma_fp16(acc[mi][nh * 2 + q], ah[mi], bh[q * 2], bh[q * 2 + 1]);
            }
        }
    }

    // ---------------- epilogue -------------------------------------------
    const int wnb = n0 + wn * 32;
    if (MODE == 0) {
        const int sIdx = wnb >> 10;
        const int h    = (wnb >> 6) & 15;
        const int dby  = (wnb & 63);
        __half* dst = (sIdx == 0) ? g_q_h : (sIdx == 1) ? g_k_h : g_v_h;
#pragma unroll
        for (int mi = 0; mi < MI; mi++)
#pragma unroll
            for (int half = 0; half < 2; half++) {
                int row = m0 + wm * (TM / 2) + mi * 16 + (lane >> 2) + half * 8;
                int b = row >> 10, l = row & 1023;
                size_t rbase = ((size_t)(b * H_ + h) * L_ + l) * HD;
#pragma unroll
                for (int ni = 0; ni < 4; ni++) {
                    int d = dby + ni * 8 + (lane & 3) * 2;
                    __half2 hv = __floats2half2_rn(acc[mi][ni][half * 2],
                                                   acc[mi][ni][half * 2 + 1]);
                    *(__half2*)&dst[rbase + d] = hv;
                }
            }
    } else {
#pragma unroll
        for (int mi = 0; mi < MI; mi++)
#pragma unroll
            for (int half = 0; half < 2; half++) {
                int row = m0 + wm * (TM / 2) + mi * 16 + (lane >> 2) + half * 8;
#pragma unroll
                for (int ni = 0; ni < 4; ni++) {
                    int n = wnb + ni * 8 + (lane & 3) * 2;
                    *(float2*)&C[(size_t)row * 1024 + n] =
                        make_float2(acc[mi][ni][half * 2], acc[mi][ni][half * 2 + 1]);
                }
            }
    }
}

#define TC_SMEM0 (3 * (128 * 128 + 16384))   // 98304
#define TC_SMEM1 (3 * (64 * 128 + 16384))    // 73728

// ---------------------------------------------------------------------------
// Flash attention (R15 + Q fragments hoisted into registers)
// ---------------------------------------------------------------------------
#define FA_Q    0
#define FA_K0   16384
#define FA_V0   24576
#define FA_K1   32768
#define FA_V1   40960
#define FA_R    49152
#define FA_QE   65536
#define FA_SMEM (65536 + 40960)   // 106496
#define QEP 80

__device__ __forceinline__ void fa_tile64(uint32_t dst, const __half* g,
                                          int rowbase, int t) {
#pragma unroll
    for (int j = 0; j < 2; j++) {
        int c = t + 256 * j;
        int row = c >> 3, ch = c & 7;
        uint32_t so = (uint32_t)(row * 128 + ((ch ^ (row & 7)) << 4));
        CP_ASYNC16(dst + so, g + (size_t)(rowbase + row) * 64 + ch * 8);
    }
}

__global__ void __launch_bounds__(256, 2) attn_flash(const float* __restrict__ rel_emb) {
    extern __shared__ char smc[];
    uint32_t sb = smem_u32(smc);
    float* qEf = (float*)(smc + FA_QE);

    const int t = threadIdx.x, lane = t & 31, warp = t >> 5;
    const int qt0 = blockIdx.x * 128;
    const int bh  = blockIdx.y;
    const int rowbase = (warp >> 2) * 64 + (warp & 3) * 16;
    const __half* gq = g_q_h + (size_t)bh * L_ * HD;
    const __half* gk = g_k_h + (size_t)bh * L_ * HD;
    const __half* gv = g_v_h + (size_t)bh * L_ * HD;

    const int a_rb = rowbase + (lane & 15);
    const int a_cb = (lane >> 4);

    int first_kb = 4 - 2 * (int)blockIdx.x;
    if (first_kb < 0) first_kb = 0;

    // ---------- phase 0 ----------------------------------------------------
    {
#pragma unroll
        for (int j = 0; j < 4; j++) {
            int c = t + 256 * j;
            int row = c >> 3, ch = c & 7;
            uint32_t so = (uint32_t)(row * 128 + ((ch ^ (row & 7)) << 4));
            CP_ASYNC16(sb + FA_Q + so, gq + (size_t)(qt0 + row) * 64 + ch * 8);
        }
        CP_COMMIT();
    }
    {
        int kb0 = qt0 - 256 + first_kb * 64;
        fa_tile64(sb + FA_K0, gk, kb0, t);
        fa_tile64(sb + FA_V0, gv, kb0, t);
        CP_COMMIT();
    }
    for (int i = t; i < 63 * 8; i += 256) {
        int row = 65 + (i >> 3), ch = i & 7;
        *(uint4*)(smc + FA_R + row * 128 + ch * 16) = make_uint4(0, 0, 0, 0);
    }
    for (int idx = t; idx < 65 * 16; idx += 256) {
        int r = idx >> 4, c4 = idx & 15;
        float4 v = *(const float4*)&rel_emb[r * HD + c4 * 4];
        *(uint2*)(smc + FA_R + sw_off4(r, c4)) = f4_to_h4(v);
    }
    CP_WAIT1();
    __syncthreads();

    // ---------- hoist Q fragments (FA_Q never overwritten) ------------------
    uint32_t qfr[4][4];
#pragma unroll
    for (int kk = 0; kk < 4; kk++) {
        int r = a_rb, c = kk * 2 + a_cb;
        ldsm_x4(qfr[kk][0], qfr[kk][1], qfr[kk][2], qfr[kk][3],
                sb + FA_Q + (uint32_t)(r * 128 + ((c ^ (r & 7)) << 4)));
    }

    // ---------- phase 1: qE = Q * R^T (warp m16 x n80) ---------------------
    {
        float qa[10][4];
#pragma unroll
        for (int ni = 0; ni < 10; ni++)
#pragma unroll
            for (int e = 0; e < 4; e++) qa[ni][e] = 0.f;
#pragma unroll
        for (int kk = 0; kk < 4; kk++) {
#pragma unroll
            for (int g = 0; g < 5; g++) {
                int r = g * 16 + ((lane >> 4) * 8) + (lane & 7);
                int c = kk * 2 + ((lane >> 3) & 1);
                uint32_t bhf[4];
                ldsm_x4(bhf[0], bhf[1], bhf[2], bhf[3],
                        sb + FA_R + (uint32_t)(r * 128 + ((c ^ (r & 7)) << 4)));
                mma_fp16(qa[g * 2], qfr[kk], bhf[0], bhf[1]);
                mma_fp16(qa[g * 2 + 1], qfr[kk], bhf[2], bhf[3]);
            }
        }
#pragma unroll
        for (int ni = 0; ni < 10; ni++)
#pragma unroll
            for (int half = 0; half < 2; half++) {
                int row = rowbase + (lane >> 2) + half * 8;
                int col = ni * 8 + (lane & 3) * 2;
                qEf[row * QEP + col]     = qa[ni][half * 2];
                qEf[row * QEP + col + 1] = qa[ni][half * 2 + 1];
            }
        __syncwarp();
    }

    // ---------- main loop --------------------------------------------------
    float oac[8][4];
#pragma unroll
    for (int ni = 0; ni < 8; ni++)
#pragma unroll
        for (int e = 0; e < 4; e++) oac[ni][e] = 0.f;
    float mrow[2] = {-1e30f, -1e30f};
    float srow[2] = {0.f, 0.f};

    const int qb = qt0 + rowbase;

    for (int kbk = first_kb; kbk < 6; kbk++) {
        int kb0 = qt0 - 256 + kbk * 64;
        int bufi = (kbk - first_kb) & 1;
        uint32_t kbase = sb + FA_K0 + bufi * 16384;

        CP_WAIT0();
        __syncthreads();
        if (kbk < 5) {
            fa_tile64(sb + FA_K0 + (1 - bufi) * 16384, gk, kb0 + 64, t);
            fa_tile64(sb + FA_V0 + (1 - bufi) * 16384, gv, kb0 + 64, t);
            CP_COMMIT();
        }

        if (kb0 > qb + 15 || kb0 + 63 <= qb - 256) continue;

        float sc[8][4];
#pragma unroll
        for (int ni = 0; ni < 8; ni++)
#pragma unroll
            for (int e = 0; e < 4; e++) sc[ni][e] = 0.f;
#pragma unroll
        for (int kk = 0; kk < 4; kk++) {
#pragma unroll
            for (int g = 0; g < 4; g++) {
                int r = g * 16 + ((lane >> 4) * 8) + (lane & 7);
                int c = kk * 2 + ((lane >> 3) & 1);
                uint32_t bhf[4];
                ldsm_x4(bhf[0], bhf[1], bhf[2], bhf[3],
                        kbase + (uint32_t)(r * 128 + ((c ^ (r & 7)) << 4)));
                mma_fp16(sc[g * 2], qfr[kk], bhf[0], bhf[1]);
                mma_fp16(sc[g * 2 + 1], qfr[kk], bhf[2], bhf[3]);
            }
        }

        const bool interior = (kb0 + 63 <= qb) && (qb + 15 - kb0 < 256);

        uint32_t pa[4][4];
#pragma unroll
        for (int h = 0; h < 2; h++) {
            int rl = rowbase + (lane >> 2) + h * 8;
            int i  = qt0 + rl;
            float mx = -1e30f;
            if (interior) {
#pragma unroll
                for (int ni = 0; ni < 8; ni++)
#pragma unroll
                    for (int dd = 0; dd < 2; dd++) {
                        int j = kb0 + ni * 8 + (lane & 3) * 2 + dd;
                        int rel = j - i + 64;
                        if (rel < 0) rel = 0;
                        float v = (sc[ni][h * 2 + dd] + qEf[rl * QEP + rel]) * 0.125f;
                        sc[ni][h * 2 + dd] = v;
                        mx = fmaxf(mx, v);
                    }
                mx = fmaxf(mx, __shfl_xor_sync(0xffffffffu, mx, 1));
                mx = fmaxf(mx, __shfl_xor_sync(0xffffffffu, mx, 2));
                float mn = fmaxf(mrow[h], mx);
                float corr = __expf(mrow[h] - mn);
                float rs = 0.f;
#pragma unroll
                for (int ni = 0; ni < 8; ni++)
#pragma unroll
                    for (int dd = 0; dd < 2; dd++) {
                        float p = __expf(sc[ni][h * 2 + dd] - mn);
                        sc[ni][h * 2 + dd] = p;
                        rs += p;
                    }
                rs += __shfl_xor_sync(0xffffffffu, rs, 1);
                rs += __shfl_xor_sync(0xffffffffu, rs, 2);
                srow[h] = srow[h] * corr + rs;
                mrow[h] = mn;
#pragma unroll
                for (int ni = 0; ni < 8; ni++) {
                    oac[ni][h * 2]     *= corr;
                    oac[ni][h * 2 + 1] *= corr;
                }
            } else {
#pragma unroll
                for (int ni = 0; ni < 8; ni++)
#pragma unroll
                    for (int dd = 0; dd < 2; dd++) {
                        int j = kb0 + ni * 8 + (lane & 3) * 2 + dd;
                        float v;
                        if (j > i || i - j >= 256) {
                            v = -1e30f;
                        } else {
                            int rel = j - i + 64;
                            if (rel < 0) rel = 0;
                            v = (sc[ni][h * 2 + dd] + qEf[rl * QEP + rel]) * 0.125f;
                        }
                        sc[ni][h * 2 + dd] = v;
                        mx = fmaxf(mx, v);
                    }
                mx = fmaxf(mx, __shfl_xor_sync(0xffffffffu, mx, 1));
                mx = fmaxf(mx, __shfl_xor_sync(0xffffffffu, mx, 2));
                bool valid = mx > -0.5e30f;
                float mn = valid ? fmaxf(mrow[h], mx) : mrow[h];
                float corr = valid ? __expf(mrow[h] - mn) : 1.f;
                float rs = 0.f;
#pragma unroll
                for (int ni = 0; ni < 8; ni++)
#pragma unroll
                    for (int dd = 0; dd < 2; dd++) {
                        float p = __expf(sc[ni][h * 2 + dd] - mn);
                        p = valid ? p : 0.f;
                        sc[ni][h * 2 + dd] = p;
                        rs += p;
                    }
                rs += __shfl_xor_sync(0xffffffffu, rs, 1);
                rs += __shfl_xor_sync(0xffffffffu, rs, 2);
                srow[h] = srow[h] * corr + rs;
                mrow[h] = mn;
#pragma unroll
                for (int ni = 0; ni < 8; ni++) {
                    oac[ni][h * 2]     *= corr;
                    oac[ni][h * 2 + 1] *= corr;
                }
            }
        }

#pragma unroll
        for (int kk = 0; kk < 4; kk++) {
            pa[kk][0] = f2_to_h2(sc[2 * kk][0],     sc[2 * kk][1]);
            pa[kk][1] = f2_to_h2(sc[2 * kk][2],     sc[2 * kk][3]);
            pa[kk][2] = f2_to_h2(sc[2 * kk + 1][0], sc[2 * kk + 1][1]);
            pa[kk][3] = f2_to_h2(sc[2 * kk + 1][2], sc[2 * kk + 1][3]);
        }

#pragma unroll
        for (int kk = 0; kk < 4; kk++) {
#pragma unroll
            for (int dch = 0; dch < 4; dch++) {
                int vrow = kk * 16 + (lane & 7) + ((lane >> 3) & 1) * 8;
                int vch  = dch * 2 + (lane >> 4);
                uint32_t bhf[4];
                ldsm_x4_t(bhf[0], bhf[1], bhf[2], bhf[3],
                          kbase + 8192 +
                          (uint32_t)(vrow * 128 + ((vch ^ (vrow & 7)) << 4)));
                mma_fp16(oac[dch * 2],     pa[kk], bhf[0], bhf[1]);
                mma_fp16(oac[dch * 2 + 1], pa[kk], bhf[2], bhf[3]);
            }
        }
    }

    // ---------- epilogue ---------------------------------------------------
    {
        int b = bh >> 4, hh = bh & 15;
#pragma unroll
        for (int h = 0; h < 2; h++) {
            float inv = 1.f / srow[h];
            int i = qt0 + rowbase + (lane >> 2) + h * 8;
#pragma unroll
            for (int ni = 0; ni < 8; ni++) {
                int d = ni * 8 + (lane & 3) * 2;
                __half2 hv = __floats2half2_rn(oac[ni][h * 2] * inv,
                                               oac[ni][h * 2 + 1] * inv);
                size_t off = ((size_t)(b * L_ + i) * H_ + hh) * HD + d;
                *(__half2*)&g_att_h[off] = hv;
            }
        }
    }
}

// ---------------------------------------------------------------------------
extern "C" void kernel_launch(void* const* d_in, const int* in_sizes, int n_in,
                              void* d_out, int out_size) {
    const float* x       = (const float*)d_in[0];
    const float* w_qkv   = (const float*)d_in[1];
    const float* w_out   = (const float*)d_in[2];
    const float* rel_emb = (const float*)d_in[3];
    float* out = (float*)d_out;

    (void)in_sizes; (void)n_in; (void)out_size;

    cudaFuncSetAttribute(attn_flash,
                         cudaFuncAttributeMaxDynamicSharedMemorySize, FA_SMEM);
    cudaFuncSetAttribute(tc_gemm<0>,
                         cudaFuncAttributeMaxDynamicSharedMemorySize, TC_SMEM0);
    cudaFuncSetAttribute(tc_gemm<1>,
                         cudaFuncAttributeMaxDynamicSharedMemorySize, TC_SMEM1);

    cvt_all<<<CVT_CH / 256, 256>>>(x, w_qkv, w_out);

    tc_gemm<0><<<dim3(3072 / 128, 4096 / 128), 256, TC_SMEM0>>>(nullptr);

    attn_flash<<<dim3(L_ / 128, NBH), 256, FA_SMEM>>>(rel_emb);

    tc_gemm<1><<<dim3(1024 / 128, 4096 / 64), 256, TC_SMEM1>>>(out);
}

// round 17
// speedup vs baseline: 1.0055x; 1.0055x over previous
#include <cuda_runtime.h>
#include <cuda_fp16.h>
#include <cstdint>

#define B_  4
#define L_  1024
#define D_  1024
#define H_  16
#define HD  64
#define NBH (B_ * H_)   // 64

// ---------------------------------------------------------------------------
// Static device scratch (no allocation allowed) — single fp16 everywhere
// ---------------------------------------------------------------------------
__device__ __half g_q_h[NBH * L_ * HD];
__device__ __half g_k_h[NBH * L_ * HD];
__device__ __half g_v_h[NBH * L_ * HD];

__device__ __half g_x_h[B_ * L_ * D_];
__device__ __half g_wqkv_h[3 * D_ * D_];
__device__ __half g_wout_h[D_ * D_];
__device__ __half g_att_h[B_ * L_ * D_];

// ---------------------------------------------------------------------------
// PTX helpers (base ISA only)
// ---------------------------------------------------------------------------
__device__ __forceinline__ uint32_t smem_u32(const void* p) {
    uint32_t a;
    asm("{ .reg .u64 t; cvta.to.shared.u64 t, %1; cvt.u32.u64 %0, t; }" : "=r"(a) : "l"(p));
    return a;
}

#define CP_ASYNC16(dst, src) \
    asm volatile("cp.async.cg.shared.global [%0], [%1], 16;" :: "r"(dst), "l"(src))
#define CP_COMMIT() asm volatile("cp.async.commit_group;" ::: "memory")
#define CP_WAIT0()  asm volatile("cp.async.wait_group 0;" ::: "memory")
#define CP_WAIT1()  asm volatile("cp.async.wait_group 1;" ::: "memory")

__device__ __forceinline__ void ldsm_x4(uint32_t& r0, uint32_t& r1, uint32_t& r2,
                                        uint32_t& r3, uint32_t addr) {
    asm volatile("ldmatrix.sync.aligned.m8n8.x4.shared.b16 {%0,%1,%2,%3}, [%4];"
                 : "=r"(r0), "=r"(r1), "=r"(r2), "=r"(r3) : "r"(addr));
}
__device__ __forceinline__ void ldsm_x4_t(uint32_t& r0, uint32_t& r1, uint32_t& r2,
                                          uint32_t& r3, uint32_t addr) {
    asm volatile("ldmatrix.sync.aligned.m8n8.x4.trans.shared.b16 {%0,%1,%2,%3}, [%4];"
                 : "=r"(r0), "=r"(r1), "=r"(r2), "=r"(r3) : "r"(addr));
}

__device__ __forceinline__ void mma_fp16(float* d, const uint32_t* a,
                                         uint32_t b0, uint32_t b1) {
    asm volatile(
        "mma.sync.aligned.m16n8k16.row.col.f32.f16.f16.f32 "
        "{%0,%1,%2,%3}, {%4,%5,%6,%7}, {%8,%9}, {%0,%1,%2,%3};"
        : "+f"(d[0]), "+f"(d[1]), "+f"(d[2]), "+f"(d[3])
        : "r"(a[0]), "r"(a[1]), "r"(a[2]), "r"(a[3]), "r"(b0), "r"(b1));
}

// fp32x4 -> packed fp16x4
__device__ __forceinline__ uint2 f4_to_h4(float4 v) {
    __half2 a = __floats2half2_rn(v.x, v.y);
    __half2 b = __floats2half2_rn(v.z, v.w);
    return make_uint2(*(uint32_t*)&a, *(uint32_t*)&b);
}
__device__ __forceinline__ uint32_t f2_to_h2(float a, float b) {
    __half2 h = __floats2half2_rn(a, b);
    return *(uint32_t*)&h;
}

// swizzled byte offset of float4-chunk c4 in a 128B-row 16-bit tile
__device__ __forceinline__ uint32_t sw_off4(int row, int c4) {
    return (uint32_t)(row * 128 + ((((c4 >> 1) ^ (row & 7)) << 4) | ((c4 & 1) << 3)));
}

// ---------------------------------------------------------------------------
// Merged fp32 -> fp16 conversion for x | w_qkv | w_out (one launch)
// ---------------------------------------------------------------------------
#define NX_CH (B_ * L_ * D_ / 4)
#define NW_CH (3 * D_ * D_ / 4)
#define NO_CH (D_ * D_ / 4)
#define CVT_CH (NX_CH + NW_CH + NO_CH)

__global__ void __launch_bounds__(256) cvt_all(const float* __restrict__ x,
                                               const float* __restrict__ wqkv,
                                               const float* __restrict__ wout) {
    int i = blockIdx.x * 256 + threadIdx.x;
    if (i < NX_CH) {
        ((uint2*)g_x_h)[i] = f4_to_h4(((const float4*)x)[i]);
    } else if (i < NX_CH + NW_CH) {
        int j = i - NX_CH;
        ((uint2*)g_wqkv_h)[j] = f4_to_h4(((const float4*)wqkv)[j]);
    } else if (i < CVT_CH) {
        int j = i - NX_CH - NW_CH;
        ((uint2*)g_wout_h)[j] = f4_to_h4(((const float4*)wout)[j]);
    }
}

// ---------------------------------------------------------------------------
// Warp-mma fp16 GEMM NT: CTA tile TM x 128 (TM=128 gemm0, 64 gemm1),
// 256 thr, 2 CTAs/SM, 3-stage cp.async, 1 sync/iter.
// MODE 0: A=x, B=w_qkv -> scatter fp16 q/k/v.  MODE 1: A=att -> C fp32.
// ---------------------------------------------------------------------------
template <int MODE>
__global__ void __launch_bounds__(256, 2) tc_gemm(float* __restrict__ C) {
    constexpr int TM   = (MODE == 0) ? 128 : 64;
    constexpr int MI   = TM / 32;
    constexpr int AT   = TM * 128;
    constexpr int STG  = AT + 16384;

    extern __shared__ char smc[];
    uint32_t sb = smem_u32(smc);

    const __half* A  = (MODE == 0) ? g_x_h : g_att_h;
    const __half* Bp = (MODE == 0) ? g_wqkv_h : g_wout_h;

    const int t = threadIdx.x, lane = t & 31, warp = t >> 5;
    const int wm = warp & 1, wn = warp >> 1;
    const int m0 = blockIdx.y * TM, n0 = blockIdx.x * 128;

    float acc[MI][4][4];
#pragma unroll
    for (int mi = 0; mi < MI; mi++)
#pragma unroll
        for (int ni = 0; ni < 4; ni++)
#pragma unroll
            for (int e = 0; e < 4; e++) acc[mi][ni][e] = 0.f;

    const int a_rb = wm * (TM / 2) + (lane & 15);
    const int a_cb = (lane >> 4);
    const int b_rb = wn * 32 + ((lane >> 4) * 8) + (lane & 7);
    const int b_cb = (lane >> 3) & 1;

    auto load_stage = [&](int it, int s) {
        uint32_t base = sb + s * STG;
        int k0 = it * 64;
#pragma unroll
        for (int j = 0; j < TM / 32; j++) {
            int c = t + 256 * j;
            int row = c >> 3, ch = c & 7;
            uint32_t so = (uint32_t)(row * 128 + ((ch ^ (row & 7)) << 4));
            CP_ASYNC16(base + so, A + (size_t)(m0 + row) * 1024 + ch * 8 + k0);
        }
#pragma unroll
        for (int j = 0; j < 4; j++) {
            int c = t + 256 * j;
            int row = c >> 3, ch = c & 7;
            uint32_t so = (uint32_t)(row * 128 + ((ch ^ (row & 7)) << 4));
            CP_ASYNC16(base + AT + so, Bp + (size_t)(n0 + row) * 1024 + ch * 8 + k0);
        }
        CP_COMMIT();
    };

    load_stage(0, 0);
    load_stage(1, 1);

    for (int it = 0; it < 16; it++) {
        int s = it % 3;
        if (it == 15) CP_WAIT0(); else CP_WAIT1();
        __syncthreads();
        if (it + 2 < 16) load_stage(it + 2, (it + 2) % 3);
        uint32_t base = sb + s * STG;

#pragma unroll
        for (int kk = 0; kk < 4; kk++) {
            uint32_t ah[MI][4];
#pragma unroll
            for (int mi = 0; mi < MI; mi++) {
                int r = a_rb + mi * 16;
                int c2 = kk * 2 + a_cb;
                uint32_t addr = base + (uint32_t)(r * 128 + ((c2 ^ (r & 7)) << 4));
                ldsm_x4(ah[mi][0], ah[mi][1], ah[mi][2], ah[mi][3], addr);
            }
#pragma unroll
            for (int nh = 0; nh < 2; nh++) {
                int r = b_rb + nh * 16;
                int c2 = kk * 2 + b_cb;
                uint32_t addr = base + AT
                              + (uint32_t)(r * 128 + ((c2 ^ (r & 7)) << 4));
                uint32_t bh[4];
                ldsm_x4(bh[0], bh[1], bh[2], bh[3], addr);
#pragma unroll
                for (int mi = 0; mi < MI; mi++)
#pragma unroll
                    for (int q = 0; q < 2; q++)
                        mma_fp16(acc[mi][nh * 2 + q], ah[mi], bh[q * 2], bh[q * 2 + 1]);
            }
        }
    }

    // ---------------- epilogue -------------------------------------------
    const int wnb = n0 + wn * 32;
    if (MODE == 0) {
        const int sIdx = wnb >> 10;
        const int h    = (wnb >> 6) & 15;
        const int dby  = (wnb & 63);
        __half* dst = (sIdx == 0) ? g_q_h : (sIdx == 1) ? g_k_h : g_v_h;
#pragma unroll
        for (int mi = 0; mi < MI; mi++)
#pragma unroll
            for (int half = 0; half < 2; half++) {
                int row = m0 + wm * (TM / 2) + mi * 16 + (lane >> 2) + half * 8;
                int b = row >> 10, l = row & 1023;
                size_t rbase = ((size_t)(b * H_ + h) * L_ + l) * HD;
#pragma unroll
                for (int ni = 0; ni < 4; ni++) {
                    int d = dby + ni * 8 + (lane & 3) * 2;
                    __half2 hv = __floats2half2_rn(acc[mi][ni][half * 2],
                                                   acc[mi][ni][half * 2 + 1]);
                    *(__half2*)&dst[rbase + d] = hv;
                }
            }
    } else {
#pragma unroll
        for (int mi = 0; mi < MI; mi++)
#pragma unroll
            for (int half = 0; half < 2; half++) {
                int row = m0 + wm * (TM / 2) + mi * 16 + (lane >> 2) + half * 8;
#pragma unroll
                for (int ni = 0; ni < 4; ni++) {
                    int n = wnb + ni * 8 + (lane & 3) * 2;
                    *(float2*)&C[(size_t)row * 1024 + n] =
                        make_float2(acc[mi][ni][half * 2], acc[mi][ni][half * 2 + 1]);
                }
            }
    }
}

#define TC_SMEM0 (3 * (128 * 128 + 16384))   // 98304
#define TC_SMEM1 (3 * (64 * 128 + 16384))    // 73728

// ---------------------------------------------------------------------------
// Flash attention (R15 version: NO Q-hoist — measured-best)
// ---------------------------------------------------------------------------
#define FA_Q    0
#define FA_K0   16384
#define FA_V0   24576
#define FA_K1   32768
#define FA_V1   40960
#define FA_R    49152
#define FA_QE   65536
#define FA_SMEM (65536 + 40960)   // 106496
#define QEP 80

__device__ __forceinline__ void fa_tile64(uint32_t dst, const __half* g,
                                          int rowbase, int t) {
#pragma unroll
    for (int j = 0; j < 2; j++) {
        int c = t + 256 * j;
        int row = c >> 3, ch = c & 7;
        uint32_t so = (uint32_t)(row * 128 + ((ch ^ (row & 7)) << 4));
        CP_ASYNC16(dst + so, g + (size_t)(rowbase + row) * 64 + ch * 8);
    }
}

__global__ void __launch_bounds__(256, 2) attn_flash(const float* __restrict__ rel_emb) {
    extern __shared__ char smc[];
    uint32_t sb = smem_u32(smc);
    float* qEf = (float*)(smc + FA_QE);

    const int t = threadIdx.x, lane = t & 31, warp = t >> 5;
    const int qt0 = blockIdx.x * 128;
    const int bh  = blockIdx.y;
    const int rowbase = (warp >> 2) * 64 + (warp & 3) * 16;
    const __half* gq = g_q_h + (size_t)bh * L_ * HD;
    const __half* gk = g_k_h + (size_t)bh * L_ * HD;
    const __half* gv = g_v_h + (size_t)bh * L_ * HD;

    const int a_rb = rowbase + (lane & 15);
    const int a_cb = (lane >> 4);

    int first_kb = 4 - 2 * (int)blockIdx.x;
    if (first_kb < 0) first_kb = 0;

    // ---------- phase 0 ----------------------------------------------------
    {
#pragma unroll
        for (int j = 0; j < 4; j++) {
            int c = t + 256 * j;
            int row = c >> 3, ch = c & 7;
            uint32_t so = (uint32_t)(row * 128 + ((ch ^ (row & 7)) << 4));
            CP_ASYNC16(sb + FA_Q + so, gq + (size_t)(qt0 + row) * 64 + ch * 8);
        }
        CP_COMMIT();
    }
    {
        int kb0 = qt0 - 256 + first_kb * 64;
        fa_tile64(sb + FA_K0, gk, kb0, t);
        fa_tile64(sb + FA_V0, gv, kb0, t);
        CP_COMMIT();
    }
    for (int i = t; i < 63 * 8; i += 256) {
        int row = 65 + (i >> 3), ch = i & 7;
        *(uint4*)(smc + FA_R + row * 128 + ch * 16) = make_uint4(0, 0, 0, 0);
    }
    for (int idx = t; idx < 65 * 16; idx += 256) {
        int r = idx >> 4, c4 = idx & 15;
        float4 v = *(const float4*)&rel_emb[r * HD + c4 * 4];
        *(uint2*)(smc + FA_R + sw_off4(r, c4)) = f4_to_h4(v);
    }
    CP_WAIT1();
    __syncthreads();

    // ---------- phase 1: qE = Q * R^T (warp m16 x n80) ---------------------
    {
        float qa[10][4];
#pragma unroll
        for (int ni = 0; ni < 10; ni++)
#pragma unroll
            for (int e = 0; e < 4; e++) qa[ni][e] = 0.f;
#pragma unroll
        for (int kk = 0; kk < 4; kk++) {
            uint32_t ah[4];
            {
                int r = a_rb, c = kk * 2 + a_cb;
                ldsm_x4(ah[0], ah[1], ah[2], ah[3],
                        sb + FA_Q + (uint32_t)(r * 128 + ((c ^ (r & 7)) << 4)));
            }
#pragma unroll
            for (int g = 0; g < 5; g++) {
                int r = g * 16 + ((lane >> 4) * 8) + (lane & 7);
                int c = kk * 2 + ((lane >> 3) & 1);
                uint32_t bhf[4];
                ldsm_x4(bhf[0], bhf[1], bhf[2], bhf[3],
                        sb + FA_R + (uint32_t)(r * 128 + ((c ^ (r & 7)) << 4)));
                mma_fp16(qa[g * 2], ah, bhf[0], bhf[1]);
                mma_fp16(qa[g * 2 + 1], ah, bhf[2], bhf[3]);
            }
        }
#pragma unroll
        for (int ni = 0; ni < 10; ni++)
#pragma unroll
            for (int half = 0; half < 2; half++) {
                int row = rowbase + (lane >> 2) + half * 8;
                int col = ni * 8 + (lane & 3) * 2;
                qEf[row * QEP + col]     = qa[ni][half * 2];
                qEf[row * QEP + col + 1] = qa[ni][half * 2 + 1];
            }
        __syncwarp();
    }

    // ---------- main loop --------------------------------------------------
    float oac[8][4];
#pragma unroll
    for (int ni = 0; ni < 8; ni++)
#pragma unroll
        for (int e = 0; e < 4; e++) oac[ni][e] = 0.f;
    float mrow[2] = {-1e30f, -1e30f};
    float srow[2] = {0.f, 0.f};

    const int qb = qt0 + rowbase;

    for (int kbk = first_kb; kbk < 6; kbk++) {
        int kb0 = qt0 - 256 + kbk * 64;
        int bufi = (kbk - first_kb) & 1;
        uint32_t kbase = sb + FA_K0 + bufi * 16384;

        CP_WAIT0();
        __syncthreads();
        if (kbk < 5) {
            fa_tile64(sb + FA_K0 + (1 - bufi) * 16384, gk, kb0 + 64, t);
            fa_tile64(sb + FA_V0 + (1 - bufi) * 16384, gv, kb0 + 64, t);
            CP_COMMIT();
        }

        if (kb0 > qb + 15 || kb0 + 63 <= qb - 256) continue;

        float sc[8][4];
#pragma unroll
        for (int ni = 0; ni < 8; ni++)
#pragma unroll
            for (int e = 0; e < 4; e++) sc[ni][e] = 0.f;
#pragma unroll
        for (int kk = 0; kk < 4; kk++) {
            uint32_t ah[4];
            {
                int r = a_rb, c = kk * 2 + a_cb;
                ldsm_x4(ah[0], ah[1], ah[2], ah[3],
                        sb + FA_Q + (uint32_t)(r * 128 + ((c ^ (r & 7)) << 4)));
            }
#pragma unroll
            for (int g = 0; g < 4; g++) {
                int r = g * 16 + ((lane >> 4) * 8) + (lane & 7);
                int c = kk * 2 + ((lane >> 3) & 1);
                uint32_t bhf[4];
                ldsm_x4(bhf[0], bhf[1], bhf[2], bhf[3],
                        kbase + (uint32_t)(r * 128 + ((c ^ (r & 7)) << 4)));
                mma_fp16(sc[g * 2], ah, bhf[0], bhf[1]);
                mma_fp16(sc[g * 2 + 1], ah, bhf[2], bhf[3]);
            }
        }

        const bool interior = (kb0 + 63 <= qb) && (qb + 15 - kb0 < 256);

        uint32_t pa[4][4];
#pragma unroll
        for (int h = 0; h < 2; h++) {
            int rl = rowbase + (lane >> 2) + h * 8;
            int i  = qt0 + rl;
            float mx = -1e30f;
            if (interior) {
#pragma unroll
                for (int ni = 0; ni < 8; ni++)
#pragma unroll
                    for (int dd = 0; dd < 2; dd++) {
                        int j = kb0 + ni * 8 + (lane & 3) * 2 + dd;
                        int rel = j - i + 64;
                        if (rel < 0) rel = 0;
                        float v = (sc[ni][h * 2 + dd] + qEf[rl * QEP + rel]) * 0.125f;
                        sc[ni][h * 2 + dd] = v;
                        mx = fmaxf(mx, v);
                    }
                mx = fmaxf(mx, __shfl_xor_sync(0xffffffffu, mx, 1));
                mx = fmaxf(mx, __shfl_xor_sync(0xffffffffu, mx, 2));
                float mn = fmaxf(mrow[h], mx);
                float corr = __expf(mrow[h] - mn);
                float rs = 0.f;
#pragma unroll
                for (int ni = 0; ni < 8; ni++)
#pragma unroll
                    for (int dd = 0; dd < 2; dd++) {
                        float p = __expf(sc[ni][h * 2 + dd] - mn);
                        sc[ni][h * 2 + dd] = p;
                        rs += p;
                    }
                rs += __shfl_xor_sync(0xffffffffu, rs, 1);
                rs += __shfl_xor_sync(0xffffffffu, rs, 2);
                srow[h] = srow[h] * corr + rs;
                mrow[h] = mn;
#pragma unroll
                for (int ni = 0; ni < 8; ni++) {
                    oac[ni][h * 2]     *= corr;
                    oac[ni][h * 2 + 1] *= corr;
                }
            } else {
#pragma unroll
                for (int ni = 0; ni < 8; ni++)
#pragma unroll
                    for (int dd = 0; dd < 2; dd++) {
                        int j = kb0 + ni * 8 + (lane & 3) * 2 + dd;
                        float v;
                        if (j > i || i - j >= 256) {
                            v = -1e30f;
                        } else {
                            int rel = j - i + 64;
                            if (rel < 0) rel = 0;
                            v = (sc[ni][h * 2 + dd] + qEf[rl * QEP + rel]) * 0.125f;
                        }
                        sc[ni][h * 2 + dd] = v;
                        mx = fmaxf(mx, v);
                    }
                mx = fmaxf(mx, __shfl_xor_sync(0xffffffffu, mx, 1));
                mx = fmaxf(mx, __shfl_xor_sync(0xffffffffu, mx, 2));
                bool valid = mx > -0.5e30f;
                float mn = valid ? fmaxf(mrow[h], mx) : mrow[h];
                float corr = valid ? __expf(mrow[h] - mn) : 1.f;
                float rs = 0.f;
#pragma unroll
                for (int ni = 0; ni < 8; ni++)
#pragma unroll
                    for (int dd = 0; dd < 2; dd++) {
                        float p = __expf(sc[ni][h * 2 + dd] - mn);
                        p = valid ? p : 0.f;
                        sc[ni][h * 2 + dd] = p;
                        rs += p;
                    }
                rs += __shfl_xor_sync(0xffffffffu, rs, 1);
                rs += __shfl_xor_sync(0xffffffffu, rs, 2);
                srow[h] = srow[h] * corr + rs;
                mrow[h] = mn;
#pragma unroll
                for (int ni = 0; ni < 8; ni++) {
                    oac[ni][h * 2]     *= corr;
                    oac[ni][h * 2 + 1] *= corr;
                }
            }
        }

#pragma unroll
        for (int kk = 0; kk < 4; kk++) {
            pa[kk][0] = f2_to_h2(sc[2 * kk][0],     sc[2 * kk][1]);
            pa[kk][1] = f2_to_h2(sc[2 * kk][2],     sc[2 * kk][3]);
            pa[kk][2] = f2_to_h2(sc[2 * kk + 1][0], sc[2 * kk + 1][1]);
            pa[kk][3] = f2_to_h2(sc[2 * kk + 1][2], sc[2 * kk + 1][3]);
        }

#pragma unroll
        for (int kk = 0; kk < 4; kk++) {
#pragma unroll
            for (int dch = 0; dch < 4; dch++) {
                int vrow = kk * 16 + (lane & 7) + ((lane >> 3) & 1) * 8;
                int vch  = dch * 2 + (lane >> 4);
                uint32_t bhf[4];
                ldsm_x4_t(bhf[0], bhf[1], bhf[2], bhf[3],
                          kbase + 8192 +
                          (uint32_t)(vrow * 128 + ((vch ^ (vrow & 7)) << 4)));
                mma_fp16(oac[dch * 2],     pa[kk], bhf[0], bhf[1]);
                mma_fp16(oac[dch * 2 + 1], pa[kk], bhf[2], bhf[3]);
            }
        }
    }

    // ---------- epilogue ---------------------------------------------------
    {
        int b = bh >> 4, hh = bh & 15;
#pragma unroll
        for (int h = 0; h < 2; h++) {
            float inv = 1.f / srow[h];
            int i = qt0 + rowbase + (lane >> 2) + h * 8;
#pragma unroll
            for (int ni = 0; ni < 8; ni++) {
                int d = ni * 8 + (lane & 3) * 2;
                __half2 hv = __floats2half2_rn(oac[ni][h * 2] * inv,
                                               oac[ni][h * 2 + 1] * inv);
                size_t off = ((size_t)(b * L_ + i) * H_ + hh) * HD + d;
                *(__half2*)&g_att_h[off] = hv;
            }
        }
    }
}

// ---------------------------------------------------------------------------
extern "C" void kernel_launch(void* const* d_in, const int* in_sizes, int n_in,
                              void* d_out, int out_size) {
    const float* x       = (const float*)d_in[0];
    const float* w_qkv   = (const float*)d_in[1];
    const float* w_out   = (const float*)d_in[2];
    const float* rel_emb = (const float*)d_in[3];
    float* out = (float*)d_out;

    (void)in_sizes; (void)n_in; (void)out_size;

    cudaFuncSetAttribute(attn_flash,
                         cudaFuncAttributeMaxDynamicSharedMemorySize, FA_SMEM);
    cudaFuncSetAttribute(tc_gemm<0>,
                         cudaFuncAttributeMaxDynamicSharedMemorySize, TC_SMEM0);
    cudaFuncSetAttribute(tc_gemm<1>,
                         cudaFuncAttributeMaxDynamicSharedMemorySize, TC_SMEM1);

    cvt_all<<<CVT_CH / 256, 256>>>(x, w_qkv, w_out);

    tc_gemm<0><<<dim3(3072 / 128, 4096 / 128), 256, TC_SMEM0>>>(nullptr);

    attn_flash<<<dim3(L_ / 128, NBH), 256, FA_SMEM>>>(rel_emb);

    tc_gemm<1><<<dim3(1024 / 128, 4096 / 64), 256, TC_SMEM1>>>(out);
}